// round 3
// baseline (speedup 1.0000x reference)
#include <cuda_runtime.h>
#include <math.h>

#define Nn 100000
#define Ee 1600000
#define Ff 128
#define NFf 4
#define Dd 64
#define NLl 3
#define Gg 128

// ---------------- device scratch (static allocations only) ----------------
static __device__ int   g_deg[Nn];
static __device__ int   g_fill[Nn];
static __device__ int   g_rowptr[Nn + 1];
static __device__ int   g_bsum[128];
static __device__ int   g_boff[128];
static __device__ int2  g_epk[NFf * Ee];               // per-factor CSR-ordered (src, att_bits)
static __device__ float g_bufA[NFf * Nn * Dd];
static __device__ float g_bufB[NFf * Nn * Dd];
static __device__ float g_cnt[Gg];
static __device__ float g_Wc[NFf * NLl * 128 * 64];    // [Wrel;Wroot] stacked per (f,l)
static __device__ float g_WT[NFf * 2 * 64 * 192];      // WihT | WhhT  [f][m][k][j]

// ---------------- f32x2 packed math helpers ----------------
__device__ __forceinline__ unsigned long long pk2(float a, float b) {
    unsigned long long r;
    asm("mov.b64 %0, {%1,%2};" : "=l"(r) : "f"(a), "f"(b));
    return r;
}
__device__ __forceinline__ float2 upk2(unsigned long long v) {
    float2 r;
    asm("mov.b64 {%0,%1}, %2;" : "=f"(r.x), "=f"(r.y) : "l"(v));
    return r;
}
__device__ __forceinline__ void fma2(unsigned long long& c, unsigned long long a, unsigned long long b) {
    asm("fma.rn.f32x2 %0, %1, %2, %0;" : "+l"(c) : "l"(a), "l"(b));
}
__device__ __forceinline__ unsigned long long dup2(float a) { return pk2(a, a); }
__device__ __forceinline__ float sigm(float x) { return 1.0f / (1.0f + expf(-x)); }

// ---------------- utility kernels ----------------
__global__ void k_zero_misc() {
    int i = blockIdx.x * blockDim.x + threadIdx.x;
    if (i < Nn) { g_deg[i] = 0; g_fill[i] = 0; }
    if (i < Gg) g_cnt[i] = 0.0f;
}

__global__ void k_zero_f(float* p, int n) {
    int i = blockIdx.x * blockDim.x + threadIdx.x;
    if (i < n) p[i] = 0.0f;
}

__global__ void k_count(const int* __restrict__ ei) {
    int e = blockIdx.x * blockDim.x + threadIdx.x;
    if (e < Ee) atomicAdd(&g_deg[ei[Ee + e]], 1);
}

// ---- parallel 3-phase scan -> exclusive rowptr ----
__global__ void k_scan1() {
    __shared__ int s[1024];
    int tid = threadIdx.x;
    int i = blockIdx.x * 1024 + tid;
    int v = (i < Nn) ? g_deg[i] : 0;
    s[tid] = v;
    __syncthreads();
    for (int off = 1; off < 1024; off <<= 1) {
        int t = (tid >= off) ? s[tid - off] : 0;
        __syncthreads();
        s[tid] += t;
        __syncthreads();
    }
    if (i < Nn) g_rowptr[i + 1] = s[tid];
    if (tid == 1023) g_bsum[blockIdx.x] = s[1023];
}

__global__ void k_scan2(int nblk) {
    if (threadIdx.x == 0) {
        int run = 0;
        g_rowptr[0] = 0;
        for (int b = 0; b < nblk; b++) { g_boff[b] = run; run += g_bsum[b]; }
    }
}

__global__ void k_scan3() {
    int i = blockIdx.x * blockDim.x + threadIdx.x;
    if (i < Nn) g_rowptr[i + 1] += g_boff[i >> 10];
}

__global__ void k_fill(const int* __restrict__ ei, const float* __restrict__ att) {
    int e = blockIdx.x * blockDim.x + threadIdx.x;
    if (e >= Ee) return;
    int d = ei[Ee + e];
    int src = ei[e];
    int pos = g_rowptr[d] + atomicAdd(&g_fill[d], 1);
#pragma unroll
    for (int f = 0; f < NFf; f++) {
        float w = att[(size_t)f * Ee + e];
        g_epk[(size_t)f * Ee + pos] = make_int2(src, __float_as_int(w));
    }
}

__global__ void k_cnt(const int* __restrict__ batch) {
    int i = blockIdx.x * blockDim.x + threadIdx.x;
    if (i < Nn) atomicAdd(&g_cnt[batch[i]], 1.0f);
}

// ---- one-shot weight repack: Wc stack + GRU transposes ----
__global__ void k_prep(const float* __restrict__ Wrel, const float* __restrict__ Wroot,
                       const float* __restrict__ Wih, const float* __restrict__ Whh) {
    int i = blockIdx.x * blockDim.x + threadIdx.x;
    // Wc: [f*NL+l][128][64]
    int nWc = NFf * NLl * 128 * 64;
    if (i < nWc) {
        int c = i & 63;
        int kk = (i >> 6) & 127;
        int fl = i >> 13;
        float v = (kk < 64) ? Wrel[((size_t)fl * 64 + kk) * 64 + c]
                            : Wroot[((size_t)fl * 64 + (kk - 64)) * 64 + c];
        g_Wc[i] = v;
    }
    // WT: [f][m][k(64)][j(192)] = W[f][j][k]
    int nWT = NFf * 2 * 64 * 192;
    if (i < nWT) {
        int j = i % 192;
        int k = (i / 192) & 63;
        int fm = i / (192 * 64);
        int m = fm & 1, f = fm >> 1;
        const float* W = m ? Whh : Wih;
        g_WT[i] = W[((size_t)f * 192 + j) * 64 + k];
    }
}

// ---------------- fused lin over 4 factors ----------------
__global__ __launch_bounds__(256) void k_lin4(const float* __restrict__ x,
                                              const float* __restrict__ lin_W,
                                              const float* __restrict__ lin_b,
                                              float* __restrict__ out) {
    extern __shared__ float sm[];
    float* sX = sm;               // 64 x 132
    float* sW = sm + 64 * 132;    // 128 x 64
    float* sB = sW + 128 * 64;    // 64
    int tid = threadIdx.x;
    int row0 = blockIdx.x * 64;

    for (int idx = tid; idx < 64 * 32; idx += 256) {
        int r = idx >> 5, q = idx & 31;
        float4 v;
        if (row0 + r < Nn) v = *(const float4*)(x + (size_t)(row0 + r) * Ff + q * 4);
        else v = make_float4(0.f, 0.f, 0.f, 0.f);
        float* d = sX + r * 132 + q * 4;
        d[0] = v.x; d[1] = v.y; d[2] = v.z; d[3] = v.w;
    }

    int ty = tid >> 4, tx = tid & 15;
    int r = ty * 4, c = tx * 4;

    for (int f = 0; f < NFf; f++) {
        __syncthreads();
        for (int idx = tid; idx < 128 * 16; idx += 256)
            *(float4*)(sW + idx * 4) = *(const float4*)(lin_W + (size_t)f * Ff * Dd + idx * 4);
        if (tid < 64) sB[tid] = lin_b[f * Dd + tid];
        __syncthreads();

        unsigned long long acc[2][4] = {};
#pragma unroll 4
        for (int k = 0; k < 128; k++) {
            unsigned long long a0 = pk2(sX[r * 132 + k], sX[(r + 1) * 132 + k]);
            unsigned long long a1 = pk2(sX[(r + 2) * 132 + k], sX[(r + 3) * 132 + k]);
            float4 bv = *(const float4*)(sW + k * 64 + c);
            unsigned long long b0 = dup2(bv.x), b1 = dup2(bv.y), b2 = dup2(bv.z), b3 = dup2(bv.w);
            fma2(acc[0][0], a0, b0); fma2(acc[0][1], a0, b1);
            fma2(acc[0][2], a0, b2); fma2(acc[0][3], a0, b3);
            fma2(acc[1][0], a1, b0); fma2(acc[1][1], a1, b1);
            fma2(acc[1][2], a1, b2); fma2(acc[1][3], a1, b3);
        }
        float* outf = out + (size_t)f * Nn * Dd;
#pragma unroll
        for (int p = 0; p < 2; p++)
#pragma unroll
            for (int j = 0; j < 4; j++) {
                float2 v = upk2(acc[p][j]);
                float bb = sB[c + j];
                int rr0 = row0 + r + 2 * p;
                if (rr0 < Nn)     outf[(size_t)rr0 * Dd + c + j]       = v.x + bb;
                if (rr0 + 1 < Nn) outf[(size_t)(rr0 + 1) * Dd + c + j] = v.y + bb;
            }
    }
}

#define FMA8(ACC, A0, A1, B4)                               \
    {                                                       \
        fma2(ACC[0][0], A0, dup2(B4.x));                    \
        fma2(ACC[0][1], A0, dup2(B4.y));                    \
        fma2(ACC[0][2], A0, dup2(B4.z));                    \
        fma2(ACC[0][3], A0, dup2(B4.w));                    \
        fma2(ACC[1][0], A1, dup2(B4.x));                    \
        fma2(ACC[1][1], A1, dup2(B4.y));                    \
        fma2(ACC[1][2], A1, dup2(B4.z));                    \
        fma2(ACC[1][3], A1, dup2(B4.w));                    \
    }

// ---------------- fused layer (all 4 factors; blockIdx.y = f) ----------------
// stage h; CSR-SpMM agg directly into shared; conv+relu; GRU; write nxt
__global__ __launch_bounds__(256) void k_layer4(const float* __restrict__ cur,
                                                float* __restrict__ nxt,
                                                int l,
                                                const float* __restrict__ brel,
                                                const float* __restrict__ bih,
                                                const float* __restrict__ bhh) {
    extern __shared__ float sm[];
    float* sIn   = sm;                 // 64 x 132  cols 0..63 = agg, 64..127 = h
    float* sM    = sIn + 64 * 132;     // 64 x 68
    float* sW    = sM + 64 * 68;       // phase1 Wc(128x64)=8192; phase2 WihT|WhhT pitch196 = 25088
    float* sBrel = sW + 25088;         // 64
    float* sBih  = sBrel + 64;         // 192
    float* sBhh  = sBih + 192;         // 192

    int tid = threadIdx.x;
    int f = blockIdx.y;
    int row0 = blockIdx.x * 64;
    const float* curf = cur + (size_t)f * Nn * Dd;
    float* nxtf = nxt + (size_t)f * Nn * Dd;

    // stage Wc (contiguous, pre-stacked)
    const float* Wc = g_Wc + (size_t)(f * NLl + l) * 128 * 64;
    for (int idx = tid; idx < 2048; idx += 256)
        *(float4*)(sW + idx * 4) = *(const float4*)(Wc + idx * 4);
    if (tid < 64) sBrel[tid] = brel[(size_t)(f * NLl + l) * Dd + tid];
    if (tid < 192) {
        sBih[tid] = bih[(size_t)f * 192 + tid];
        sBhh[tid] = bhh[(size_t)f * 192 + tid];
    }

    // stage h (cols 64..127)
    for (int idx = tid; idx < 64 * 16; idx += 256) {
        int r = idx >> 4, q = idx & 15;
        int grow = row0 + r;
        float4 v = (grow < Nn) ? *(const float4*)(curf + (size_t)grow * Dd + q * 4)
                               : make_float4(0.f, 0.f, 0.f, 0.f);
        float* d = sIn + r * 132 + 64 + q * 4;
        d[0] = v.x; d[1] = v.y; d[2] = v.z; d[3] = v.w;
    }

    // fused CSR SpMM into cols 0..63 (warp per row, 8 rows per warp)
    {
        int wid = tid >> 5, lane = tid & 31;
        const int2* ep = g_epk + (size_t)f * Ee;
        for (int rr = wid; rr < 64; rr += 8) {
            int row = row0 + rr;
            float ax = 0.f, ay = 0.f;
            if (row < Nn) {
                int beg = g_rowptr[row], end = g_rowptr[row + 1];
#pragma unroll 4
                for (int j = beg; j < end; j++) {
                    int2 pe = ep[j];
                    float w = __int_as_float(pe.y);
                    float2 v = *(const float2*)(curf + (size_t)pe.x * Dd + lane * 2);
                    ax = fmaf(v.x, w, ax);
                    ay = fmaf(v.y, w, ay);
                }
            }
            sIn[rr * 132 + lane * 2]     = ax;
            sIn[rr * 132 + lane * 2 + 1] = ay;
        }
    }
    __syncthreads();

    int ty = tid >> 4, tx = tid & 15;
    int r = ty * 4, c = tx * 4;

    // phase 1: m tile
    {
        unsigned long long acc[2][4] = {};
#pragma unroll 4
        for (int k = 0; k < 128; k++) {
            unsigned long long a0 = pk2(sIn[r * 132 + k], sIn[(r + 1) * 132 + k]);
            unsigned long long a1 = pk2(sIn[(r + 2) * 132 + k], sIn[(r + 3) * 132 + k]);
            float4 bv = *(const float4*)(sW + k * 64 + c);
            FMA8(acc, a0, a1, bv);
        }
#pragma unroll
        for (int p = 0; p < 2; p++)
#pragma unroll
            for (int j = 0; j < 4; j++) {
                float2 v = upk2(acc[p][j]);
                float bb = sBrel[c + j];
                sM[(r + 2 * p) * 68 + c + j]     = fmaxf(v.x + bb, 0.f);
                sM[(r + 2 * p + 1) * 68 + c + j] = fmaxf(v.y + bb, 0.f);
            }
    }
    __syncthreads();

    // stage WihT|WhhT from pre-transposed global (coalesced float4)
    for (int idx = tid; idx < 6144; idx += 256) {
        int m = (idx >= 3072) ? 1 : 0;
        int t = idx - m * 3072;
        int k = t / 48, q = t - k * 48;
        float4 v = *(const float4*)(g_WT + ((size_t)(f * 2 + m) * 64 + k) * 192 + q * 4);
        *(float4*)(sW + m * 12544 + k * 196 + q * 4) = v;
    }
    __syncthreads();

    const float* sWih = sW;
    const float* sWhh = sW + 12544;

    unsigned long long ir[2][4] = {}, iz[2][4] = {}, in_[2][4] = {};
    unsigned long long hr[2][4] = {}, hz[2][4] = {}, hn[2][4] = {};
#pragma unroll 2
    for (int k = 0; k < 64; k++) {
        unsigned long long am0 = pk2(sM[r * 68 + k], sM[(r + 1) * 68 + k]);
        unsigned long long am1 = pk2(sM[(r + 2) * 68 + k], sM[(r + 3) * 68 + k]);
        unsigned long long ah0 = pk2(sIn[r * 132 + 64 + k], sIn[(r + 1) * 132 + 64 + k]);
        unsigned long long ah1 = pk2(sIn[(r + 2) * 132 + 64 + k], sIn[(r + 3) * 132 + 64 + k]);
        float4 bir = *(const float4*)(sWih + k * 196 + c);
        float4 biz = *(const float4*)(sWih + k * 196 + 64 + c);
        float4 bin = *(const float4*)(sWih + k * 196 + 128 + c);
        float4 bhr = *(const float4*)(sWhh + k * 196 + c);
        float4 bhz = *(const float4*)(sWhh + k * 196 + 64 + c);
        float4 bhn = *(const float4*)(sWhh + k * 196 + 128 + c);
        FMA8(ir, am0, am1, bir);
        FMA8(iz, am0, am1, biz);
        FMA8(in_, am0, am1, bin);
        FMA8(hr, ah0, ah1, bhr);
        FMA8(hz, ah0, ah1, bhz);
        FMA8(hn, ah0, ah1, bhn);
    }

#pragma unroll
    for (int p = 0; p < 2; p++) {
        int rloc = r + 2 * p;
#pragma unroll
        for (int j = 0; j < 4; j++) {
            int cc = c + j;
            float2 vir = upk2(ir[p][j]), viz = upk2(iz[p][j]), vin = upk2(in_[p][j]);
            float2 vhr = upk2(hr[p][j]), vhz = upk2(hz[p][j]), vhn = upk2(hn[p][j]);
            float b_r = sBih[cc] + sBhh[cc];
            float b_zi = sBih[64 + cc], b_zh = sBhh[64 + cc];
            float b_ni = sBih[128 + cc], b_nh = sBhh[128 + cc];
            {
                float rr = sigm(vir.x + vhr.x + b_r);
                float zz = sigm(viz.x + b_zi + vhz.x + b_zh);
                float nn = tanhf(vin.x + b_ni + rr * (vhn.x + b_nh));
                float hc = sIn[rloc * 132 + 64 + cc];
                if (row0 + rloc < Nn)
                    nxtf[(size_t)(row0 + rloc) * Dd + cc] = (1.f - zz) * nn + zz * hc;
            }
            {
                float rr = sigm(vir.y + vhr.y + b_r);
                float zz = sigm(viz.y + b_zi + vhz.y + b_zh);
                float nn = tanhf(vin.y + b_ni + rr * (vhn.y + b_nh));
                float hc = sIn[(rloc + 1) * 132 + 64 + cc];
                if (row0 + rloc + 1 < Nn)
                    nxtf[(size_t)(row0 + rloc + 1) * Dd + cc] = (1.f - zz) * nn + zz * hc;
            }
        }
    }
}

// ---------------- mean pool (batch sorted; blockIdx.y = f) ----------------
__global__ void k_pool4(const float* __restrict__ feats, const int* __restrict__ batch,
                        float* __restrict__ outs) {
    int f = blockIdx.y;
    const float* feat = feats + (size_t)f * Nn * Dd;
    float* outf = outs + (size_t)f * Gg * Dd;
    int x = threadIdx.x;
    int yg = threadIdx.y;
    int base = blockIdx.x * 256 + yg * 64;
    float acc = 0.0f;
    int g = -1;
    for (int i = 0; i < 64; i++) {
        int row = base + i;
        if (row >= Nn) break;
        int b = batch[row];
        if (b != g) {
            if (g >= 0) atomicAdd(&outf[g * Dd + x], acc);
            g = b;
            acc = 0.0f;
        }
        acc += feat[(size_t)row * Dd + x];
    }
    if (g >= 0) atomicAdd(&outf[g * Dd + x], acc);
}

__global__ void k_div(float* outs) {
    int i = blockIdx.x * blockDim.x + threadIdx.x;
    if (i < NFf * Gg * Dd) {
        int g = (i >> 6) & (Gg - 1);
        float cval = fmaxf(g_cnt[g], 1.0f);
        outs[i] /= cval;
    }
}

// ---------------- host orchestration ----------------
extern "C" void kernel_launch(void* const* d_in, const int* in_sizes, int n_in,
                              void* d_out, int out_size) {
    const float* x     = (const float*)d_in[0];
    const int*   ei    = (const int*)d_in[1];
    const float* att   = (const float*)d_in[2];
    const int*   batch = (const int*)d_in[3];
    const float* lin_W = (const float*)d_in[4];
    const float* lin_b = (const float*)d_in[5];
    const float* Wrel  = (const float*)d_in[6];
    const float* brel  = (const float*)d_in[7];
    const float* Wroot = (const float*)d_in[8];
    const float* Wih   = (const float*)d_in[9];
    const float* Whh   = (const float*)d_in[10];
    const float* bih   = (const float*)d_in[11];
    const float* bhh   = (const float*)d_in[12];

    float* outp  = (float*)d_out;
    float* outs  = outp;                              // [4,128,64]
    float* feats = outp + (size_t)NFf * Gg * Dd;      // [4,N,64]

    cudaFuncSetAttribute(k_layer4, cudaFuncAttributeMaxDynamicSharedMemorySize, 38336 * 4);
    cudaFuncSetAttribute(k_lin4, cudaFuncAttributeMaxDynamicSharedMemorySize, 16704 * 4);

    float* bufA;
    float* bufB;
    cudaGetSymbolAddress((void**)&bufA, g_bufA);
    cudaGetSymbolAddress((void**)&bufB, g_bufB);

    int nscan = (Nn + 1023) / 1024;

    k_zero_misc<<<(Nn + 255) / 256, 256>>>();
    k_zero_f<<<(NFf * Gg * Dd + 255) / 256, 256>>>(outs, NFf * Gg * Dd);
    k_count<<<(Ee + 255) / 256, 256>>>(ei);
    k_scan1<<<nscan, 1024>>>();
    k_scan2<<<1, 32>>>(nscan);
    k_scan3<<<nscan, 1024>>>();
    k_fill<<<(Ee + 255) / 256, 256>>>(ei, att);
    k_cnt<<<(Nn + 255) / 256, 256>>>(batch);
    {
        int nprep = NFf * NLl * 128 * 64;   // >= NFf*2*64*192
        k_prep<<<(nprep + 255) / 256, 256>>>(Wrel, Wroot, Wih, Whh);
    }

    int nb64 = (Nn + 63) / 64;

    k_lin4<<<nb64, 256, 16704 * 4>>>(x, lin_W, lin_b, bufA);

    float* cur = bufA;
    for (int l = 0; l < NLl; l++) {
        float* nxt = (l == NLl - 1) ? feats : ((l == 0) ? bufB : bufA);
        k_layer4<<<dim3(nb64, NFf), 256, 38336 * 4>>>(cur, nxt, l, brel, bih, bhh);
        cur = nxt;
    }
    k_pool4<<<dim3((Nn + 255) / 256, NFf), dim3(64, 4)>>>(feats, batch, outs);
    k_div<<<(NFf * Gg * Dd + 255) / 256, 256>>>(outs);
}

// round 4
// speedup vs baseline: 1.6750x; 1.6750x over previous
#include <cuda_runtime.h>
#include <math.h>

#define Nn 100000
#define Ee 1600000
#define Ff 128
#define NFf 4
#define Dd 64
#define NLl 3
#define Gg 128

// ---------------- device scratch (static allocations only) ----------------
static __device__ int   g_deg[Nn];
static __device__ int   g_fill[Nn];
static __device__ int   g_rowptr[Nn + 1];
static __device__ int   g_bsum[128];
static __device__ int   g_boff[128];
static __device__ int2  g_epk[NFf * Ee];               // per-factor CSR-ordered (src, att_bits)
static __device__ float g_agg[NFf * Nn * Dd];
static __device__ float g_bufA[NFf * Nn * Dd];
static __device__ float g_bufB[NFf * Nn * Dd];
static __device__ float g_cnt[Gg];
static __device__ float g_Wc[NFf * NLl * 128 * 64];    // [Wrel;Wroot] stacked per (f,l)
static __device__ float g_WT[NFf * 2 * 64 * 192];      // WihT | WhhT  [f][m][k][j]

// ---------------- f32x2 packed math helpers ----------------
__device__ __forceinline__ unsigned long long pk2(float a, float b) {
    unsigned long long r;
    asm("mov.b64 %0, {%1,%2};" : "=l"(r) : "f"(a), "f"(b));
    return r;
}
__device__ __forceinline__ float2 upk2(unsigned long long v) {
    float2 r;
    asm("mov.b64 {%0,%1}, %2;" : "=f"(r.x), "=f"(r.y) : "l"(v));
    return r;
}
__device__ __forceinline__ void fma2(unsigned long long& c, unsigned long long a, unsigned long long b) {
    asm("fma.rn.f32x2 %0, %1, %2, %0;" : "+l"(c) : "l"(a), "l"(b));
}
__device__ __forceinline__ unsigned long long dup2(float a) { return pk2(a, a); }
__device__ __forceinline__ float sigm(float x) { return 1.0f / (1.0f + expf(-x)); }

// ---------------- utility kernels ----------------
__global__ void k_zero_misc() {
    int i = blockIdx.x * blockDim.x + threadIdx.x;
    if (i < Nn) { g_deg[i] = 0; g_fill[i] = 0; }
    if (i < Gg) g_cnt[i] = 0.0f;
}

__global__ void k_zero_f(float* p, int n) {
    int i = blockIdx.x * blockDim.x + threadIdx.x;
    if (i < n) p[i] = 0.0f;
}

__global__ void k_count(const int* __restrict__ ei) {
    int e = blockIdx.x * blockDim.x + threadIdx.x;
    if (e < Ee) atomicAdd(&g_deg[ei[Ee + e]], 1);
}

// ---- parallel 3-phase scan -> exclusive rowptr ----
__global__ void k_scan1() {
    __shared__ int s[1024];
    int tid = threadIdx.x;
    int i = blockIdx.x * 1024 + tid;
    int v = (i < Nn) ? g_deg[i] : 0;
    s[tid] = v;
    __syncthreads();
    for (int off = 1; off < 1024; off <<= 1) {
        int t = (tid >= off) ? s[tid - off] : 0;
        __syncthreads();
        s[tid] += t;
        __syncthreads();
    }
    if (i < Nn) g_rowptr[i + 1] = s[tid];
    if (tid == 1023) g_bsum[blockIdx.x] = s[1023];
}

__global__ void k_scan2(int nblk) {
    if (threadIdx.x == 0) {
        int run = 0;
        g_rowptr[0] = 0;
        for (int b = 0; b < nblk; b++) { g_boff[b] = run; run += g_bsum[b]; }
    }
}

__global__ void k_scan3() {
    int i = blockIdx.x * blockDim.x + threadIdx.x;
    if (i < Nn) g_rowptr[i + 1] += g_boff[i >> 10];
}

__global__ void k_fill(const int* __restrict__ ei, const float* __restrict__ att) {
    int e = blockIdx.x * blockDim.x + threadIdx.x;
    if (e >= Ee) return;
    int d = ei[Ee + e];
    int src = ei[e];
    int pos = g_rowptr[d] + atomicAdd(&g_fill[d], 1);
#pragma unroll
    for (int f = 0; f < NFf; f++) {
        float w = att[(size_t)f * Ee + e];
        g_epk[(size_t)f * Ee + pos] = make_int2(src, __float_as_int(w));
    }
}

__global__ void k_cnt(const int* __restrict__ batch) {
    int i = blockIdx.x * blockDim.x + threadIdx.x;
    if (i < Nn) atomicAdd(&g_cnt[batch[i]], 1.0f);
}

// ---- one-shot weight repack: Wc stack + GRU transposes ----
__global__ void k_prep(const float* __restrict__ Wrel, const float* __restrict__ Wroot,
                       const float* __restrict__ Wih, const float* __restrict__ Whh) {
    int i = blockIdx.x * blockDim.x + threadIdx.x;
    int nWc = NFf * NLl * 128 * 64;
    if (i < nWc) {
        int c = i & 63;
        int kk = (i >> 6) & 127;
        int fl = i >> 13;
        float v = (kk < 64) ? Wrel[((size_t)fl * 64 + kk) * 64 + c]
                            : Wroot[((size_t)fl * 64 + (kk - 64)) * 64 + c];
        g_Wc[i] = v;
    }
    int nWT = NFf * 2 * 64 * 192;
    if (i < nWT) {
        int j = i % 192;
        int k = (i / 192) & 63;
        int fm = i / (192 * 64);
        int m = fm & 1, f = fm >> 1;
        const float* W = m ? Whh : Wih;
        g_WT[i] = W[((size_t)f * 192 + j) * 64 + k];
    }
}

// ---------------- SpMM (standalone, high occupancy; blockIdx.y = f) --------
__global__ __launch_bounds__(256) void k_spmm4(const float* __restrict__ cur) {
    int f = blockIdx.y;
    int warp = (blockIdx.x * blockDim.x + threadIdx.x) >> 5;
    int lane = threadIdx.x & 31;
    if (warp >= Nn) return;
    const float* curf = cur + (size_t)f * Nn * Dd;
    float* aggf = g_agg + (size_t)f * Nn * Dd;
    int beg = g_rowptr[warp], end = g_rowptr[warp + 1];
    const int2* ep = g_epk + (size_t)f * Ee;
    float ax = 0.0f, ay = 0.0f;
#pragma unroll 4
    for (int j = beg; j < end; j++) {
        int2 pe = ep[j];
        float w = __int_as_float(pe.y);
        float2 v = *(const float2*)(curf + (size_t)pe.x * Dd + lane * 2);
        ax = fmaf(v.x, w, ax);
        ay = fmaf(v.y, w, ay);
    }
    *(float2*)(aggf + (size_t)warp * Dd + lane * 2) = make_float2(ax, ay);
}

// ---------------- fused lin over 4 factors ----------------
__global__ __launch_bounds__(256) void k_lin4(const float* __restrict__ x,
                                              const float* __restrict__ lin_W,
                                              const float* __restrict__ lin_b,
                                              float* __restrict__ out) {
    extern __shared__ float sm[];
    float* sX = sm;               // 64 x 132
    float* sW = sm + 64 * 132;    // 128 x 64
    float* sB = sW + 128 * 64;    // 64
    int tid = threadIdx.x;
    int row0 = blockIdx.x * 64;

    for (int idx = tid; idx < 64 * 32; idx += 256) {
        int r = idx >> 5, q = idx & 31;
        float4 v;
        if (row0 + r < Nn) v = *(const float4*)(x + (size_t)(row0 + r) * Ff + q * 4);
        else v = make_float4(0.f, 0.f, 0.f, 0.f);
        float* d = sX + r * 132 + q * 4;
        d[0] = v.x; d[1] = v.y; d[2] = v.z; d[3] = v.w;
    }

    int ty = tid >> 4, tx = tid & 15;
    int r = ty * 4, c = tx * 4;

    for (int f = 0; f < NFf; f++) {
        __syncthreads();
        for (int idx = tid; idx < 128 * 16; idx += 256)
            *(float4*)(sW + idx * 4) = *(const float4*)(lin_W + (size_t)f * Ff * Dd + idx * 4);
        if (tid < 64) sB[tid] = lin_b[f * Dd + tid];
        __syncthreads();

        unsigned long long acc[2][4] = {};
#pragma unroll 4
        for (int k = 0; k < 128; k++) {
            unsigned long long a0 = pk2(sX[r * 132 + k], sX[(r + 1) * 132 + k]);
            unsigned long long a1 = pk2(sX[(r + 2) * 132 + k], sX[(r + 3) * 132 + k]);
            float4 bv = *(const float4*)(sW + k * 64 + c);
            unsigned long long b0 = dup2(bv.x), b1 = dup2(bv.y), b2 = dup2(bv.z), b3 = dup2(bv.w);
            fma2(acc[0][0], a0, b0); fma2(acc[0][1], a0, b1);
            fma2(acc[0][2], a0, b2); fma2(acc[0][3], a0, b3);
            fma2(acc[1][0], a1, b0); fma2(acc[1][1], a1, b1);
            fma2(acc[1][2], a1, b2); fma2(acc[1][3], a1, b3);
        }
        float* outf = out + (size_t)f * Nn * Dd;
#pragma unroll
        for (int p = 0; p < 2; p++)
#pragma unroll
            for (int j = 0; j < 4; j++) {
                float2 v = upk2(acc[p][j]);
                float bb = sB[c + j];
                int rr0 = row0 + r + 2 * p;
                if (rr0 < Nn)     outf[(size_t)rr0 * Dd + c + j]       = v.x + bb;
                if (rr0 + 1 < Nn) outf[(size_t)(rr0 + 1) * Dd + c + j] = v.y + bb;
            }
    }
}

#define FMA8(ACC, A0, A1, B4)                               \
    {                                                       \
        fma2(ACC[0][0], A0, dup2(B4.x));                    \
        fma2(ACC[0][1], A0, dup2(B4.y));                    \
        fma2(ACC[0][2], A0, dup2(B4.z));                    \
        fma2(ACC[0][3], A0, dup2(B4.w));                    \
        fma2(ACC[1][0], A1, dup2(B4.x));                    \
        fma2(ACC[1][1], A1, dup2(B4.y));                    \
        fma2(ACC[1][2], A1, dup2(B4.z));                    \
        fma2(ACC[1][3], A1, dup2(B4.w));                    \
    }

// ---------------- fused layer (all 4 factors; blockIdx.y = f) ----------------
// smem ~100.7KB -> 2 blocks/SM. Weights staged in 3 passes over one sW buffer.
__global__ __launch_bounds__(256, 2) void k_layer4(const float* __restrict__ cur,
                                                   float* __restrict__ nxt,
                                                   int l,
                                                   const float* __restrict__ brel,
                                                   const float* __restrict__ bih,
                                                   const float* __restrict__ bhh) {
    extern __shared__ float sm[];
    float* sIn   = sm;                 // 64 x 132  cols 0..63 = agg, 64..127 = h
    float* sM    = sIn + 64 * 132;     // 64 x 68
    float* sW    = sM + 64 * 68;       // 12544: Wc(8192) then WihT then WhhT (pitch 196)
    float* sBrel = sW + 12544;         // 64
    float* sBih  = sBrel + 64;         // 192
    float* sBhh  = sBih + 192;         // 192
    // total 25792 floats = 103168 B

    int tid = threadIdx.x;
    int f = blockIdx.y;
    int row0 = blockIdx.x * 64;
    const float* curf = cur + (size_t)f * Nn * Dd;
    const float* aggf = g_agg + (size_t)f * Nn * Dd;
    float* nxtf = nxt + (size_t)f * Nn * Dd;

    // stage Wc (contiguous, pre-stacked) + biases
    const float* Wc = g_Wc + (size_t)(f * NLl + l) * 128 * 64;
    for (int idx = tid; idx < 2048; idx += 256)
        *(float4*)(sW + idx * 4) = *(const float4*)(Wc + idx * 4);
    if (tid < 64) sBrel[tid] = brel[(size_t)(f * NLl + l) * Dd + tid];
    if (tid < 192) {
        sBih[tid] = bih[(size_t)f * 192 + tid];
        sBhh[tid] = bhh[(size_t)f * 192 + tid];
    }

    // stage [agg | h]
    for (int idx = tid; idx < 64 * 32; idx += 256) {
        int r = idx >> 5, q = idx & 31;
        int grow = row0 + r;
        float4 v;
        if (grow < Nn) {
            if (q < 16) v = *(const float4*)(aggf + (size_t)grow * Dd + q * 4);
            else        v = *(const float4*)(curf + (size_t)grow * Dd + (q - 16) * 4);
        } else v = make_float4(0.f, 0.f, 0.f, 0.f);
        float* d = sIn + r * 132 + ((q < 16) ? q * 4 : 64 + (q - 16) * 4);
        d[0] = v.x; d[1] = v.y; d[2] = v.z; d[3] = v.w;
    }
    __syncthreads();

    int ty = tid >> 4, tx = tid & 15;
    int r = ty * 4, c = tx * 4;

    // phase 1: m tile
    {
        unsigned long long acc[2][4] = {};
#pragma unroll 4
        for (int k = 0; k < 128; k++) {
            unsigned long long a0 = pk2(sIn[r * 132 + k], sIn[(r + 1) * 132 + k]);
            unsigned long long a1 = pk2(sIn[(r + 2) * 132 + k], sIn[(r + 3) * 132 + k]);
            float4 bv = *(const float4*)(sW + k * 64 + c);
            FMA8(acc, a0, a1, bv);
        }
#pragma unroll
        for (int p = 0; p < 2; p++)
#pragma unroll
            for (int j = 0; j < 4; j++) {
                float2 v = upk2(acc[p][j]);
                float bb = sBrel[c + j];
                sM[(r + 2 * p) * 68 + c + j]     = fmaxf(v.x + bb, 0.f);
                sM[(r + 2 * p + 1) * 68 + c + j] = fmaxf(v.y + bb, 0.f);
            }
    }
    __syncthreads();

    // stage WihT (pitch 196)
    for (int idx = tid; idx < 3072; idx += 256) {
        int k = idx / 48, q = idx - k * 48;
        float4 v = *(const float4*)(g_WT + ((size_t)(f * 2 + 0) * 64 + k) * 192 + q * 4);
        *(float4*)(sW + k * 196 + q * 4) = v;
    }
    __syncthreads();

    unsigned long long ir[2][4] = {}, iz[2][4] = {}, in_[2][4] = {};
#pragma unroll 2
    for (int k = 0; k < 64; k++) {
        unsigned long long am0 = pk2(sM[r * 68 + k], sM[(r + 1) * 68 + k]);
        unsigned long long am1 = pk2(sM[(r + 2) * 68 + k], sM[(r + 3) * 68 + k]);
        float4 bir = *(const float4*)(sW + k * 196 + c);
        float4 biz = *(const float4*)(sW + k * 196 + 64 + c);
        float4 bin = *(const float4*)(sW + k * 196 + 128 + c);
        FMA8(ir, am0, am1, bir);
        FMA8(iz, am0, am1, biz);
        FMA8(in_, am0, am1, bin);
    }
    __syncthreads();

    // stage WhhT (overwrite sW)
    for (int idx = tid; idx < 3072; idx += 256) {
        int k = idx / 48, q = idx - k * 48;
        float4 v = *(const float4*)(g_WT + ((size_t)(f * 2 + 1) * 64 + k) * 192 + q * 4);
        *(float4*)(sW + k * 196 + q * 4) = v;
    }
    __syncthreads();

    unsigned long long hr[2][4] = {}, hz[2][4] = {}, hn[2][4] = {};
#pragma unroll 2
    for (int k = 0; k < 64; k++) {
        unsigned long long ah0 = pk2(sIn[r * 132 + 64 + k], sIn[(r + 1) * 132 + 64 + k]);
        unsigned long long ah1 = pk2(sIn[(r + 2) * 132 + 64 + k], sIn[(r + 3) * 132 + 64 + k]);
        float4 bhr = *(const float4*)(sW + k * 196 + c);
        float4 bhz = *(const float4*)(sW + k * 196 + 64 + c);
        float4 bhn = *(const float4*)(sW + k * 196 + 128 + c);
        FMA8(hr, ah0, ah1, bhr);
        FMA8(hz, ah0, ah1, bhz);
        FMA8(hn, ah0, ah1, bhn);
    }

#pragma unroll
    for (int p = 0; p < 2; p++) {
        int rloc = r + 2 * p;
#pragma unroll
        for (int j = 0; j < 4; j++) {
            int cc = c + j;
            float2 vir = upk2(ir[p][j]), viz = upk2(iz[p][j]), vin = upk2(in_[p][j]);
            float2 vhr = upk2(hr[p][j]), vhz = upk2(hz[p][j]), vhn = upk2(hn[p][j]);
            float b_r = sBih[cc] + sBhh[cc];
            float b_zi = sBih[64 + cc], b_zh = sBhh[64 + cc];
            float b_ni = sBih[128 + cc], b_nh = sBhh[128 + cc];
            {
                float rr = sigm(vir.x + vhr.x + b_r);
                float zz = sigm(viz.x + b_zi + vhz.x + b_zh);
                float nn = tanhf(vin.x + b_ni + rr * (vhn.x + b_nh));
                float hc = sIn[rloc * 132 + 64 + cc];
                if (row0 + rloc < Nn)
                    nxtf[(size_t)(row0 + rloc) * Dd + cc] = (1.f - zz) * nn + zz * hc;
            }
            {
                float rr = sigm(vir.y + vhr.y + b_r);
                float zz = sigm(viz.y + b_zi + vhz.y + b_zh);
                float nn = tanhf(vin.y + b_ni + rr * (vhn.y + b_nh));
                float hc = sIn[(rloc + 1) * 132 + 64 + cc];
                if (row0 + rloc + 1 < Nn)
                    nxtf[(size_t)(row0 + rloc + 1) * Dd + cc] = (1.f - zz) * nn + zz * hc;
            }
        }
    }
}

// ---------------- mean pool (batch sorted; blockIdx.y = f) ----------------
__global__ void k_pool4(const float* __restrict__ feats, const int* __restrict__ batch,
                        float* __restrict__ outs) {
    int f = blockIdx.y;
    const float* feat = feats + (size_t)f * Nn * Dd;
    float* outf = outs + (size_t)f * Gg * Dd;
    int x = threadIdx.x;
    int yg = threadIdx.y;
    int base = blockIdx.x * 256 + yg * 64;
    float acc = 0.0f;
    int g = -1;
    for (int i = 0; i < 64; i++) {
        int row = base + i;
        if (row >= Nn) break;
        int b = batch[row];
        if (b != g) {
            if (g >= 0) atomicAdd(&outf[g * Dd + x], acc);
            g = b;
            acc = 0.0f;
        }
        acc += feat[(size_t)row * Dd + x];
    }
    if (g >= 0) atomicAdd(&outf[g * Dd + x], acc);
}

__global__ void k_div(float* outs) {
    int i = blockIdx.x * blockDim.x + threadIdx.x;
    if (i < NFf * Gg * Dd) {
        int g = (i >> 6) & (Gg - 1);
        float cval = fmaxf(g_cnt[g], 1.0f);
        outs[i] /= cval;
    }
}

// ---------------- host orchestration ----------------
extern "C" void kernel_launch(void* const* d_in, const int* in_sizes, int n_in,
                              void* d_out, int out_size) {
    const float* x     = (const float*)d_in[0];
    const int*   ei    = (const int*)d_in[1];
    const float* att   = (const float*)d_in[2];
    const int*   batch = (const int*)d_in[3];
    const float* lin_W = (const float*)d_in[4];
    const float* lin_b = (const float*)d_in[5];
    const float* Wrel  = (const float*)d_in[6];
    const float* brel  = (const float*)d_in[7];
    const float* Wroot = (const float*)d_in[8];
    const float* Wih   = (const float*)d_in[9];
    const float* Whh   = (const float*)d_in[10];
    const float* bih   = (const float*)d_in[11];
    const float* bhh   = (const float*)d_in[12];

    float* outp  = (float*)d_out;
    float* outs  = outp;                              // [4,128,64]
    float* feats = outp + (size_t)NFf * Gg * Dd;      // [4,N,64]

    cudaFuncSetAttribute(k_layer4, cudaFuncAttributeMaxDynamicSharedMemorySize, 25792 * 4);
    cudaFuncSetAttribute(k_lin4, cudaFuncAttributeMaxDynamicSharedMemorySize, 16704 * 4);

    float* bufA;
    float* bufB;
    cudaGetSymbolAddress((void**)&bufA, g_bufA);
    cudaGetSymbolAddress((void**)&bufB, g_bufB);

    int nscan = (Nn + 1023) / 1024;

    k_zero_misc<<<(Nn + 255) / 256, 256>>>();
    k_zero_f<<<(NFf * Gg * Dd + 255) / 256, 256>>>(outs, NFf * Gg * Dd);
    k_count<<<(Ee + 255) / 256, 256>>>(ei);
    k_scan1<<<nscan, 1024>>>();
    k_scan2<<<1, 32>>>(nscan);
    k_scan3<<<nscan, 1024>>>();
    k_fill<<<(Ee + 255) / 256, 256>>>(ei, att);
    k_cnt<<<(Nn + 255) / 256, 256>>>(batch);
    {
        int nprep = NFf * NLl * 128 * 64;
        k_prep<<<(nprep + 255) / 256, 256>>>(Wrel, Wroot, Wih, Whh);
    }

    int nb64 = (Nn + 63) / 64;
    int spmm_bx = (Nn * 32 + 255) / 256;

    k_lin4<<<nb64, 256, 16704 * 4>>>(x, lin_W, lin_b, bufA);

    float* cur = bufA;
    for (int l = 0; l < NLl; l++) {
        float* nxt = (l == NLl - 1) ? feats : ((l == 0) ? bufB : bufA);
        k_spmm4<<<dim3(spmm_bx, NFf), 256>>>(cur);
        k_layer4<<<dim3(nb64, NFf), 256, 25792 * 4>>>(cur, nxt, l, brel, bih, bhh);
        cur = nxt;
    }
    k_pool4<<<dim3((Nn + 255) / 256, NFf), dim3(64, 4)>>>(feats, batch, outs);
    k_div<<<(NFf * Gg * Dd + 255) / 256, 256>>>(outs);
}

// round 5
// speedup vs baseline: 1.9848x; 1.1849x over previous
#include <cuda_runtime.h>
#include <math.h>

#define Nn 100000
#define Ee 1600000
#define Ff 128
#define NFf 4
#define Dd 64
#define NLl 3
#define Gg 128

// ---------------- device scratch (static allocations only) ----------------
static __device__ int   g_deg[Nn];
static __device__ int   g_fill[Nn];
static __device__ int   g_rowptr[Nn + 1];
static __device__ int   g_bsum[128];
static __device__ int   g_boff[128];
static __device__ int2  g_epk[NFf * Ee];               // per-factor CSR-ordered (src, att_bits)
static __device__ float g_agg[NFf * Nn * Dd];
static __device__ float g_bufA[NFf * Nn * Dd];
static __device__ float g_bufB[NFf * Nn * Dd];
static __device__ float g_cnt[Gg];
static __device__ float g_Wc[NFf * NLl * 128 * 64];    // [Wrel;Wroot] stacked per (f,l)
static __device__ float g_WT[NFf * 2 * 64 * 192];      // WihT | WhhT  [f][m][k][j]

// ---------------- f32x2 packed math helpers ----------------
__device__ __forceinline__ unsigned long long pk2(float a, float b) {
    unsigned long long r;
    asm("mov.b64 %0, {%1,%2};" : "=l"(r) : "f"(a), "f"(b));
    return r;
}
__device__ __forceinline__ float2 upk2(unsigned long long v) {
    float2 r;
    asm("mov.b64 {%0,%1}, %2;" : "=f"(r.x), "=f"(r.y) : "l"(v));
    return r;
}
__device__ __forceinline__ void fma2(unsigned long long& c, unsigned long long a, unsigned long long b) {
    asm("fma.rn.f32x2 %0, %1, %2, %0;" : "+l"(c) : "l"(a), "l"(b));
}
__device__ __forceinline__ unsigned long long dup2(float a) { return pk2(a, a); }
__device__ __forceinline__ float sigm(float x) { return 1.0f / (1.0f + expf(-x)); }

// ---------------- utility kernels ----------------
__global__ void k_zero_misc() {
    int i = blockIdx.x * blockDim.x + threadIdx.x;
    if (i < Nn) { g_deg[i] = 0; g_fill[i] = 0; }
    if (i < Gg) g_cnt[i] = 0.0f;
}

__global__ void k_zero_f(float* p, int n) {
    int i = blockIdx.x * blockDim.x + threadIdx.x;
    if (i < n) p[i] = 0.0f;
}

__global__ void k_count(const int* __restrict__ ei) {
    int e = blockIdx.x * blockDim.x + threadIdx.x;
    if (e < Ee) atomicAdd(&g_deg[ei[Ee + e]], 1);
}

// ---- parallel 3-phase scan -> exclusive rowptr ----
__global__ void k_scan1() {
    __shared__ int s[1024];
    int tid = threadIdx.x;
    int i = blockIdx.x * 1024 + tid;
    int v = (i < Nn) ? g_deg[i] : 0;
    s[tid] = v;
    __syncthreads();
    for (int off = 1; off < 1024; off <<= 1) {
        int t = (tid >= off) ? s[tid - off] : 0;
        __syncthreads();
        s[tid] += t;
        __syncthreads();
    }
    if (i < Nn) g_rowptr[i + 1] = s[tid];
    if (tid == 1023) g_bsum[blockIdx.x] = s[1023];
}

__global__ void k_scan2(int nblk) {
    if (threadIdx.x == 0) {
        int run = 0;
        g_rowptr[0] = 0;
        for (int b = 0; b < nblk; b++) { g_boff[b] = run; run += g_bsum[b]; }
    }
}

__global__ void k_scan3() {
    int i = blockIdx.x * blockDim.x + threadIdx.x;
    if (i < Nn) g_rowptr[i + 1] += g_boff[i >> 10];
}

__global__ void k_fill(const int* __restrict__ ei, const float* __restrict__ att) {
    int e = blockIdx.x * blockDim.x + threadIdx.x;
    if (e >= Ee) return;
    int d = ei[Ee + e];
    int src = ei[e];
    int pos = g_rowptr[d] + atomicAdd(&g_fill[d], 1);
#pragma unroll
    for (int f = 0; f < NFf; f++) {
        float w = att[(size_t)f * Ee + e];
        g_epk[(size_t)f * Ee + pos] = make_int2(src, __float_as_int(w));
    }
}

__global__ void k_cnt(const int* __restrict__ batch) {
    int i = blockIdx.x * blockDim.x + threadIdx.x;
    if (i < Nn) atomicAdd(&g_cnt[batch[i]], 1.0f);
}

// ---- one-shot weight repack: Wc stack + GRU transposes ----
__global__ void k_prep(const float* __restrict__ Wrel, const float* __restrict__ Wroot,
                       const float* __restrict__ Wih, const float* __restrict__ Whh) {
    int i = blockIdx.x * blockDim.x + threadIdx.x;
    int nWc = NFf * NLl * 128 * 64;
    if (i < nWc) {
        int c = i & 63;
        int kk = (i >> 6) & 127;
        int fl = i >> 13;
        float v = (kk < 64) ? Wrel[((size_t)fl * 64 + kk) * 64 + c]
                            : Wroot[((size_t)fl * 64 + (kk - 64)) * 64 + c];
        g_Wc[i] = v;
    }
    int nWT = NFf * 2 * 64 * 192;
    if (i < nWT) {
        int j = i % 192;
        int k = (i / 192) & 63;
        int fm = i / (192 * 64);
        int m = fm & 1, f = fm >> 1;
        const float* W = m ? Whh : Wih;
        g_WT[i] = W[((size_t)f * 192 + j) * 64 + k];
    }
}

// ---------------- SpMM (standalone, high occupancy; blockIdx.y = f) --------
__global__ __launch_bounds__(256) void k_spmm4(const float* __restrict__ cur) {
    int f = blockIdx.y;
    int warp = (blockIdx.x * blockDim.x + threadIdx.x) >> 5;
    int lane = threadIdx.x & 31;
    if (warp >= Nn) return;
    const float* curf = cur + (size_t)f * Nn * Dd;
    float* aggf = g_agg + (size_t)f * Nn * Dd;
    int beg = g_rowptr[warp], end = g_rowptr[warp + 1];
    const int2* ep = g_epk + (size_t)f * Ee;
    float ax = 0.0f, ay = 0.0f;
#pragma unroll 4
    for (int j = beg; j < end; j++) {
        int2 pe = ep[j];
        float w = __int_as_float(pe.y);
        float2 v = *(const float2*)(curf + (size_t)pe.x * Dd + lane * 2);
        ax = fmaf(v.x, w, ax);
        ay = fmaf(v.y, w, ay);
    }
    *(float2*)(aggf + (size_t)warp * Dd + lane * 2) = make_float2(ax, ay);
}

// ---------------- fused lin over 4 factors (transposed A staging) ----------
__global__ __launch_bounds__(256) void k_lin4(const float* __restrict__ x,
                                              const float* __restrict__ lin_W,
                                              const float* __restrict__ lin_b,
                                              float* __restrict__ out) {
    extern __shared__ float sm[];
    float* sXT = sm;               // [128][68]  k-major
    float* sW  = sm + 128 * 68;    // 128 x 64
    float* sB  = sW + 128 * 64;    // 64
    int tid = threadIdx.x;
    int row0 = blockIdx.x * 64;

    // stage x transposed: sXT[k][r]
    {
        int r = tid & 63;
        int qq = tid >> 6;               // 0..3
        int grow = row0 + r;
#pragma unroll
        for (int it = 0; it < 8; it++) {
            int q = qq * 8 + it;         // 0..31 (float4 group over 128 cols)
            float4 v = (grow < Nn) ? *(const float4*)(x + (size_t)grow * Ff + q * 4)
                                   : make_float4(0.f, 0.f, 0.f, 0.f);
            int kb = q * 4;
            sXT[(kb + 0) * 68 + r] = v.x;
            sXT[(kb + 1) * 68 + r] = v.y;
            sXT[(kb + 2) * 68 + r] = v.z;
            sXT[(kb + 3) * 68 + r] = v.w;
        }
    }

    int ty = tid >> 4, tx = tid & 15;
    int r = ty * 4, c = tx * 4;

    for (int f = 0; f < NFf; f++) {
        __syncthreads();
        for (int idx = tid; idx < 128 * 16; idx += 256)
            *(float4*)(sW + idx * 4) = *(const float4*)(lin_W + (size_t)f * Ff * Dd + idx * 4);
        if (tid < 64) sB[tid] = lin_b[f * Dd + tid];
        __syncthreads();

        unsigned long long acc[2][4] = {};
#pragma unroll 4
        for (int k = 0; k < 128; k++) {
            float4 av = *(const float4*)(sXT + k * 68 + r);
            unsigned long long a0 = pk2(av.x, av.y);
            unsigned long long a1 = pk2(av.z, av.w);
            float4 bv = *(const float4*)(sW + k * 64 + c);
            unsigned long long b0 = dup2(bv.x), b1 = dup2(bv.y), b2 = dup2(bv.z), b3 = dup2(bv.w);
            fma2(acc[0][0], a0, b0); fma2(acc[0][1], a0, b1);
            fma2(acc[0][2], a0, b2); fma2(acc[0][3], a0, b3);
            fma2(acc[1][0], a1, b0); fma2(acc[1][1], a1, b1);
            fma2(acc[1][2], a1, b2); fma2(acc[1][3], a1, b3);
        }
        float* outf = out + (size_t)f * Nn * Dd;
#pragma unroll
        for (int p = 0; p < 2; p++)
#pragma unroll
            for (int j = 0; j < 4; j++) {
                float2 v = upk2(acc[p][j]);
                float bb = sB[c + j];
                int rr0 = row0 + r + 2 * p;
                if (rr0 < Nn)     outf[(size_t)rr0 * Dd + c + j]       = v.x + bb;
                if (rr0 + 1 < Nn) outf[(size_t)(rr0 + 1) * Dd + c + j] = v.y + bb;
            }
    }
}

#define FMA8(ACC, A0, A1, B4)                               \
    {                                                       \
        fma2(ACC[0][0], A0, dup2(B4.x));                    \
        fma2(ACC[0][1], A0, dup2(B4.y));                    \
        fma2(ACC[0][2], A0, dup2(B4.z));                    \
        fma2(ACC[0][3], A0, dup2(B4.w));                    \
        fma2(ACC[1][0], A1, dup2(B4.x));                    \
        fma2(ACC[1][1], A1, dup2(B4.y));                    \
        fma2(ACC[1][2], A1, dup2(B4.z));                    \
        fma2(ACC[1][3], A1, dup2(B4.w));                    \
    }

// ---------------- fused layer (all 4 factors; blockIdx.y = f) ----------------
// Transposed A staging: all A-operand reads are conflict-free LDS.128.
// smem = 26048 floats = 104192 B -> 2 blocks/SM.
__global__ __launch_bounds__(256, 2) void k_layer4(const float* __restrict__ cur,
                                                   float* __restrict__ nxt,
                                                   int l,
                                                   const float* __restrict__ brel,
                                                   const float* __restrict__ bih,
                                                   const float* __restrict__ bhh) {
    extern __shared__ float sm[];
    float* sInT  = sm;                 // [128][68]  k 0..63 = agg, 64..127 = h
    float* sMT   = sInT + 128 * 68;    // [64][68]
    float* sW    = sMT + 64 * 68;      // 12544: Wc(128x64) then WihT then WhhT (pitch 196)
    float* sBrel = sW + 12544;         // 64
    float* sBih  = sBrel + 64;         // 192
    float* sBhh  = sBih + 192;         // 192

    int tid = threadIdx.x;
    int f = blockIdx.y;
    int row0 = blockIdx.x * 64;
    const float* curf = cur + (size_t)f * Nn * Dd;
    const float* aggf = g_agg + (size_t)f * Nn * Dd;
    float* nxtf = nxt + (size_t)f * Nn * Dd;

    // stage Wc (contiguous, pre-stacked) + biases
    const float* Wc = g_Wc + (size_t)(f * NLl + l) * 128 * 64;
    for (int idx = tid; idx < 2048; idx += 256)
        *(float4*)(sW + idx * 4) = *(const float4*)(Wc + idx * 4);
    if (tid < 64) sBrel[tid] = brel[(size_t)(f * NLl + l) * Dd + tid];
    if (tid < 192) {
        sBih[tid] = bih[(size_t)f * 192 + tid];
        sBhh[tid] = bhh[(size_t)f * 192 + tid];
    }

    // stage [agg | h] transposed: sInT[k][r]
    {
        int r = tid & 63;
        int qq = tid >> 6;               // 0..3
        int grow = row0 + r;
#pragma unroll
        for (int it = 0; it < 8; it++) {
            int q = qq * 8 + it;         // 0..31
            const float* srcp = (q < 16) ? aggf : curf;
            int qc = q & 15;
            float4 v = (grow < Nn) ? *(const float4*)(srcp + (size_t)grow * Dd + qc * 4)
                                   : make_float4(0.f, 0.f, 0.f, 0.f);
            int kb = q * 4;              // 0..124
            sInT[(kb + 0) * 68 + r] = v.x;
            sInT[(kb + 1) * 68 + r] = v.y;
            sInT[(kb + 2) * 68 + r] = v.z;
            sInT[(kb + 3) * 68 + r] = v.w;
        }
    }
    __syncthreads();

    int ty = tid >> 4, tx = tid & 15;
    int r = ty * 4, c = tx * 4;

    // phase 1: m tile -> sMT (transposed)
    {
        unsigned long long acc[2][4] = {};
#pragma unroll 4
        for (int k = 0; k < 128; k++) {
            float4 av = *(const float4*)(sInT + k * 68 + r);
            unsigned long long a0 = pk2(av.x, av.y);
            unsigned long long a1 = pk2(av.z, av.w);
            float4 bv = *(const float4*)(sW + k * 64 + c);
            FMA8(acc, a0, a1, bv);
        }
#pragma unroll
        for (int p = 0; p < 2; p++)
#pragma unroll
            for (int j = 0; j < 4; j++) {
                float2 v = upk2(acc[p][j]);
                float bb = sBrel[c + j];
                sMT[(c + j) * 68 + r + 2 * p]     = fmaxf(v.x + bb, 0.f);
                sMT[(c + j) * 68 + r + 2 * p + 1] = fmaxf(v.y + bb, 0.f);
            }
    }
    __syncthreads();

    // stage WihT (pitch 196)
    for (int idx = tid; idx < 3072; idx += 256) {
        int k = idx / 48, q = idx - k * 48;
        float4 v = *(const float4*)(g_WT + ((size_t)(f * 2 + 0) * 64 + k) * 192 + q * 4);
        *(float4*)(sW + k * 196 + q * 4) = v;
    }
    __syncthreads();

    unsigned long long ir[2][4] = {}, iz[2][4] = {}, in_[2][4] = {};
#pragma unroll 2
    for (int k = 0; k < 64; k++) {
        float4 amv = *(const float4*)(sMT + k * 68 + r);
        unsigned long long am0 = pk2(amv.x, amv.y);
        unsigned long long am1 = pk2(amv.z, amv.w);
        float4 bir = *(const float4*)(sW + k * 196 + c);
        float4 biz = *(const float4*)(sW + k * 196 + 64 + c);
        float4 bin = *(const float4*)(sW + k * 196 + 128 + c);
        FMA8(ir, am0, am1, bir);
        FMA8(iz, am0, am1, biz);
        FMA8(in_, am0, am1, bin);
    }
    __syncthreads();

    // stage WhhT (overwrite sW)
    for (int idx = tid; idx < 3072; idx += 256) {
        int k = idx / 48, q = idx - k * 48;
        float4 v = *(const float4*)(g_WT + ((size_t)(f * 2 + 1) * 64 + k) * 192 + q * 4);
        *(float4*)(sW + k * 196 + q * 4) = v;
    }
    __syncthreads();

    unsigned long long hr[2][4] = {}, hz[2][4] = {}, hn[2][4] = {};
#pragma unroll 2
    for (int k = 0; k < 64; k++) {
        float4 ahv = *(const float4*)(sInT + (64 + k) * 68 + r);
        unsigned long long ah0 = pk2(ahv.x, ahv.y);
        unsigned long long ah1 = pk2(ahv.z, ahv.w);
        float4 bhr = *(const float4*)(sW + k * 196 + c);
        float4 bhz = *(const float4*)(sW + k * 196 + 64 + c);
        float4 bhn = *(const float4*)(sW + k * 196 + 128 + c);
        FMA8(hr, ah0, ah1, bhr);
        FMA8(hz, ah0, ah1, bhz);
        FMA8(hn, ah0, ah1, bhn);
    }

#pragma unroll
    for (int p = 0; p < 2; p++) {
        int rloc = r + 2 * p;
#pragma unroll
        for (int j = 0; j < 4; j++) {
            int cc = c + j;
            float2 vir = upk2(ir[p][j]), viz = upk2(iz[p][j]), vin = upk2(in_[p][j]);
            float2 vhr = upk2(hr[p][j]), vhz = upk2(hz[p][j]), vhn = upk2(hn[p][j]);
            float b_r = sBih[cc] + sBhh[cc];
            float b_zi = sBih[64 + cc], b_zh = sBhh[64 + cc];
            float b_ni = sBih[128 + cc], b_nh = sBhh[128 + cc];
            {
                float rr = sigm(vir.x + vhr.x + b_r);
                float zz = sigm(viz.x + b_zi + vhz.x + b_zh);
                float nn = tanhf(vin.x + b_ni + rr * (vhn.x + b_nh));
                float hc = sInT[(64 + cc) * 68 + rloc];
                if (row0 + rloc < Nn)
                    nxtf[(size_t)(row0 + rloc) * Dd + cc] = (1.f - zz) * nn + zz * hc;
            }
            {
                float rr = sigm(vir.y + vhr.y + b_r);
                float zz = sigm(viz.y + b_zi + vhz.y + b_zh);
                float nn = tanhf(vin.y + b_ni + rr * (vhn.y + b_nh));
                float hc = sInT[(64 + cc) * 68 + rloc + 1];
                if (row0 + rloc + 1 < Nn)
                    nxtf[(size_t)(row0 + rloc + 1) * Dd + cc] = (1.f - zz) * nn + zz * hc;
            }
        }
    }
}

// ---------------- mean pool (batch sorted; blockIdx.y = f) ----------------
__global__ void k_pool4(const float* __restrict__ feats, const int* __restrict__ batch,
                        float* __restrict__ outs) {
    int f = blockIdx.y;
    const float* feat = feats + (size_t)f * Nn * Dd;
    float* outf = outs + (size_t)f * Gg * Dd;
    int x = threadIdx.x;
    int yg = threadIdx.y;
    int base = blockIdx.x * 256 + yg * 64;
    float acc = 0.0f;
    int g = -1;
    for (int i = 0; i < 64; i++) {
        int row = base + i;
        if (row >= Nn) break;
        int b = batch[row];
        if (b != g) {
            if (g >= 0) atomicAdd(&outf[g * Dd + x], acc);
            g = b;
            acc = 0.0f;
        }
        acc += feat[(size_t)row * Dd + x];
    }
    if (g >= 0) atomicAdd(&outf[g * Dd + x], acc);
}

__global__ void k_div(float* outs) {
    int i = blockIdx.x * blockDim.x + threadIdx.x;
    if (i < NFf * Gg * Dd) {
        int g = (i >> 6) & (Gg - 1);
        float cval = fmaxf(g_cnt[g], 1.0f);
        outs[i] /= cval;
    }
}

// ---------------- host orchestration ----------------
extern "C" void kernel_launch(void* const* d_in, const int* in_sizes, int n_in,
                              void* d_out, int out_size) {
    const float* x     = (const float*)d_in[0];
    const int*   ei    = (const int*)d_in[1];
    const float* att   = (const float*)d_in[2];
    const int*   batch = (const int*)d_in[3];
    const float* lin_W = (const float*)d_in[4];
    const float* lin_b = (const float*)d_in[5];
    const float* Wrel  = (const float*)d_in[6];
    const float* brel  = (const float*)d_in[7];
    const float* Wroot = (const float*)d_in[8];
    const float* Wih   = (const float*)d_in[9];
    const float* Whh   = (const float*)d_in[10];
    const float* bih   = (const float*)d_in[11];
    const float* bhh   = (const float*)d_in[12];

    float* outp  = (float*)d_out;
    float* outs  = outp;                              // [4,128,64]
    float* feats = outp + (size_t)NFf * Gg * Dd;      // [4,N,64]

    cudaFuncSetAttribute(k_layer4, cudaFuncAttributeMaxDynamicSharedMemorySize, 26048 * 4);
    cudaFuncSetAttribute(k_lin4, cudaFuncAttributeMaxDynamicSharedMemorySize, 16960 * 4);

    float* bufA;
    float* bufB;
    cudaGetSymbolAddress((void**)&bufA, g_bufA);
    cudaGetSymbolAddress((void**)&bufB, g_bufB);

    int nscan = (Nn + 1023) / 1024;

    k_zero_misc<<<(Nn + 255) / 256, 256>>>();
    k_zero_f<<<(NFf * Gg * Dd + 255) / 256, 256>>>(outs, NFf * Gg * Dd);
    k_count<<<(Ee + 255) / 256, 256>>>(ei);
    k_scan1<<<nscan, 1024>>>();
    k_scan2<<<1, 32>>>(nscan);
    k_scan3<<<nscan, 1024>>>();
    k_fill<<<(Ee + 255) / 256, 256>>>(ei, att);
    k_cnt<<<(Nn + 255) / 256, 256>>>(batch);
    {
        int nprep = NFf * NLl * 128 * 64;
        k_prep<<<(nprep + 255) / 256, 256>>>(Wrel, Wroot, Wih, Whh);
    }

    int nb64 = (Nn + 63) / 64;
    int spmm_bx = (Nn * 32 + 255) / 256;

    k_lin4<<<nb64, 256, 16960 * 4>>>(x, lin_W, lin_b, bufA);

    float* cur = bufA;
    for (int l = 0; l < NLl; l++) {
        float* nxt = (l == NLl - 1) ? feats : ((l == 0) ? bufB : bufA);
        k_spmm4<<<dim3(spmm_bx, NFf), 256>>>(cur);
        k_layer4<<<dim3(nb64, NFf), 256, 26048 * 4>>>(cur, nxt, l, brel, bih, bhh);
        cur = nxt;
    }
    k_pool4<<<dim3((Nn + 255) / 256, NFf), dim3(64, 4)>>>(feats, batch, outs);
    k_div<<<(NFf * Gg * Dd + 255) / 256, 256>>>(outs);
}